// round 17
// baseline (speedup 1.0000x reference)
#include <cuda_runtime.h>
#include <cuda_bf16.h>
#include <cuda_fp16.h>
#include <math.h>

#define NN 10000
#define NE 256000
#define HH 128
#define H2 256
#define H3 384
#define NR 20

typedef unsigned int u32;

// ---------------- scratch (static device globals; no allocation) ----------------
__device__ __half g_x16[NN * H3];                  // node MLP out, fp16
__device__ __half g_mu16[NN * 3 * HH];             // mu fp16 (gather copy)
__device__ __half g_filters[(size_t)NE * H3];
__device__ float4 g_uv4[NE];
__device__ int    g_src[NE];
__device__ int    g_epos[NE];
__device__ u32   g_bhp[(HH / 2) * H3];
__device__ u32   g_f1h[16 * HH];
__device__ u32   g_i1h[(HH / 2) * H3];
__device__ u32   g_i2h[(H3 / 2) * H3];
__device__ u32   g_vch[(HH / 2) * H2];
__device__ u32   g_m1h[(H2 / 2) * H3];
__device__ u32   g_m2h[(H3 / 2) * H3];
__device__ float g_qmid[NN * HH];
__device__ float g_mumid[NN * 3 * HH];
__device__ float g_vnorm[NN * HH];
__device__ float g_inner[NN * HH];
__device__ float g_muw[NN * 3 * HH];
__device__ int   g_count[NN];
__device__ int   g_off[NN + 1];
__device__ int   g_cursor[NN];

__device__ __forceinline__ float silu_f(float x) {
    return x / (1.0f + __expf(-x));
}

__device__ __forceinline__ u32 pack_f16x2(float lo, float hi) {
    __half2 h = __floats2half2_rn(lo, hi);
    return *(u32*)&h;
}

__device__ __forceinline__ void mma_f16(float& c0, float& c1, float& c2, float& c3,
                                        u32 a0, u32 a1, u32 a2, u32 a3,
                                        u32 b0, u32 b1) {
    asm("mma.sync.aligned.m16n8k16.row.col.f32.f16.f16.f32 "
        "{%0,%1,%2,%3}, {%4,%5,%6,%7}, {%8,%9}, {%0,%1,%2,%3};"
        : "+f"(c0), "+f"(c1), "+f"(c2), "+f"(c3)
        : "r"(a0), "r"(a1), "r"(a2), "r"(a3), "r"(b0), "r"(b1));
}

__device__ __forceinline__ void ldsm_x4(u32& r0, u32& r1, u32& r2, u32& r3,
                                        const u32* p) {
    u32 addr = (u32)__cvta_generic_to_shared(p);
    asm volatile("ldmatrix.sync.aligned.m8n8.x4.shared.b16 {%0,%1,%2,%3}, [%4];"
                 : "=r"(r0), "=r"(r1), "=r"(r2), "=r"(r3) : "r"(addr));
}

__device__ __forceinline__ void split_pair_f16(float v0, float v1, u32& hi, u32& lo) {
    __half2 h = __floats2half2_rn(v0, v1);
    hi = *(u32*)&h;
    lo = pack_f16x2(v0 - __half2float(__low2half(h)),
                    v1 - __half2float(__high2half(h)));
}

// ---------------- merged prologue ----------------
__device__ __forceinline__ void do_pack16(const float* __restrict__ W,
                                          u32* __restrict__ dst, int idx, int width) {
    int p = idx / width, col = idx % width;
    dst[idx] = pack_f16x2(W[(2 * p) * width + col], W[(2 * p + 1) * width + col]);
}

#define SEG0 24576
#define SEG1 49152
#define SEG2 122880
#define SEG3 139264
#define SEG4 188416
#define SEG5 262144
#define SEGW 264192
#define SEG7 274192          // count zero end
#define SEG8 (SEG7 + (NN * 3 * HH) / 2)   // mu -> fp16 pairs
__global__ void k_prep(const float* __restrict__ Wf2, const float* __restrict__ Wi1,
                       const float* __restrict__ Wi2, const float* __restrict__ Wv,
                       const float* __restrict__ Wm1, const float* __restrict__ Wm2,
                       const float* __restrict__ Wf1, const float* __restrict__ mu) {
    int i = blockIdx.x * blockDim.x + threadIdx.x;
    if (i < SEG0)       do_pack16(Wf2, g_bhp, i, H3);
    else if (i < SEG1)  do_pack16(Wi1, g_i1h, i - SEG0, H3);
    else if (i < SEG2)  do_pack16(Wi2, g_i2h, i - SEG1, H3);
    else if (i < SEG3)  do_pack16(Wv,  g_vch, i - SEG2, H2);
    else if (i < SEG4)  do_pack16(Wm1, g_m1h, i - SEG3, H3);
    else if (i < SEG5)  do_pack16(Wm2, g_m2h, i - SEG4, H3);
    else if (i < SEGW) {
        int j = i - SEG5;
        int p = j >> 7, col = j & 127;
        float w0 = (2 * p < NR)     ? Wf1[(2 * p) * HH + col]     : 0.f;
        float w1 = (2 * p + 1 < NR) ? Wf1[(2 * p + 1) * HH + col] : 0.f;
        g_f1h[j] = pack_f16x2(w0, w1);
    }
    else if (i < SEG7)  g_count[i - SEGW] = 0;
    else if (i < SEG8) {
        int j = i - SEG7;
        float2 v = *(const float2*)&mu[2 * j];
        *(__half2*)&g_mu16[2 * j] = __floats2half2_rn(v.x, v.y);
    }
}

// ---------------- CSR build ----------------
__global__ void k_count(const int* __restrict__ ei) {
    for (int e = blockIdx.x * blockDim.x + threadIdx.x; e < NE;
         e += gridDim.x * blockDim.x)
        atomicAdd(&g_count[ei[e]], 1);
}

__global__ __launch_bounds__(1024) void k_scan() {
    __shared__ int wsum[32];
    int tid = threadIdx.x;
    const int CH = 10;
    int base = tid * CH;
    int vals[CH];
    int s = 0;
    #pragma unroll
    for (int j = 0; j < CH; ++j) {
        int idx = base + j;
        vals[j] = (idx < NN) ? g_count[idx] : 0;
        s += vals[j];
    }
    int lane = tid & 31, w = tid >> 5;
    int x = s;
    #pragma unroll
    for (int o = 1; o < 32; o <<= 1) {
        int v = __shfl_up_sync(0xFFFFFFFFu, x, o);
        if (lane >= o) x += v;
    }
    if (lane == 31) wsum[w] = x;
    __syncthreads();
    if (w == 0) {
        int y = wsum[lane];
        #pragma unroll
        for (int o = 1; o < 32; o <<= 1) {
            int v = __shfl_up_sync(0xFFFFFFFFu, y, o);
            if (lane >= o) y += v;
        }
        wsum[lane] = y;
    }
    __syncthreads();
    int run = x - s + (w > 0 ? wsum[w - 1] : 0);
    #pragma unroll
    for (int j = 0; j < CH; ++j) {
        int idx = base + j;
        if (idx < NN) {
            g_off[idx] = run;
            g_cursor[idx] = run;
            run += vals[j];
        }
    }
    if (tid == 1023) g_off[NN] = run;
}

__global__ void k_fill(const int* __restrict__ ei, const float* __restrict__ uv) {
    for (int e = blockIdx.x * blockDim.x + threadIdx.x; e < NE;
         e += gridDim.x * blockDim.x) {
        int t = ei[e];
        int pos = atomicAdd(&g_cursor[t], 1);
        g_epos[e] = pos;
        g_src[pos] = ei[NE + e];
        g_uv4[pos] = make_float4(uv[3 * e], uv[3 * e + 1], uv[3 * e + 2], 0.f);
    }
}

// ---------------- node inter MLP: pre-split A + ldmatrix, fp16 2-term mma ----------------
#define NQP 68
#define NHP 196
#define NODE_SMEM ((2 * 32 * NQP + 2 * 32 * NHP) * 4)
__global__ __launch_bounds__(256) void k_node_mlp(
    const float* __restrict__ q,
    const float* __restrict__ b1, const float* __restrict__ b2)
{
    extern __shared__ u32 smn[];
    u32* sqh = smn;
    u32* sql = sqh + 32 * NQP;
    u32* shh = sql + 32 * NQP;
    u32* shl = shh + 32 * NHP;
    int tid = threadIdx.x;
    int n0 = blockIdx.x * 32;

    for (int i = tid; i < 32 * 64; i += 256) {
        int r = i >> 6, kp = i & 63;
        int n = n0 + r;
        float2 v = (n < NN) ? *(const float2*)&q[n * HH + 2 * kp]
                            : make_float2(0.f, 0.f);
        u32 h, l;
        split_pair_f16(v.x, v.y, h, l);
        sqh[r * NQP + kp] = h;
        sql[r * NQP + kp] = l;
    }
    __syncthreads();

    int wid  = tid >> 5;
    int lane = tid & 31;
    int gid  = lane >> 2;
    int tig  = lane & 3;
    int nbase = wid * 48;

    {
        float acc[2][6][4];
        #pragma unroll
        for (int r = 0; r < 2; ++r)
            #pragma unroll
            for (int t = 0; t < 6; ++t)
                #pragma unroll
                for (int c = 0; c < 4; ++c) acc[r][t][c] = 0.f;

        #pragma unroll 1
        for (int k0 = 0; k0 < HH; k0 += 16) {
            int kp = k0 >> 1;
            u32 bh[6][2];
            #pragma unroll
            for (int t = 0; t < 6; ++t) {
                int col = nbase + t * 8 + gid;
                bh[t][0] = __ldg(&g_i1h[(kp + tig) * H3 + col]);
                bh[t][1] = __ldg(&g_i1h[(kp + 4 + tig) * H3 + col]);
            }
            #pragma unroll
            for (int r = 0; r < 2; ++r) {
                int loff = (r * 16 + (lane & 15)) * NQP + kp + ((lane >> 4) << 2);
                u32 ah0, ah1, ah2, ah3, al0, al1, al2, al3;
                ldsm_x4(ah0, ah1, ah2, ah3, &sqh[loff]);
                ldsm_x4(al0, al1, al2, al3, &sql[loff]);
                #pragma unroll
                for (int t = 0; t < 6; ++t) {
                    mma_f16(acc[r][t][0], acc[r][t][1], acc[r][t][2], acc[r][t][3],
                            ah0, ah1, ah2, ah3, bh[t][0], bh[t][1]);
                    mma_f16(acc[r][t][0], acc[r][t][1], acc[r][t][2], acc[r][t][3],
                            al0, al1, al2, al3, bh[t][0], bh[t][1]);
                }
            }
        }
        #pragma unroll
        for (int r = 0; r < 2; ++r) {
            int row0 = r * 16 + gid;
            int row1 = row0 + 8;
            #pragma unroll
            for (int t = 0; t < 6; ++t) {
                int col = nbase + t * 8 + 2 * tig;
                int kpo = col >> 1;
                float b0v = __ldg(&b1[col]);
                float b1v = __ldg(&b1[col + 1]);
                u32 h, l;
                split_pair_f16(silu_f(acc[r][t][0] + b0v), silu_f(acc[r][t][1] + b1v), h, l);
                shh[row0 * NHP + kpo] = h;
                shl[row0 * NHP + kpo] = l;
                split_pair_f16(silu_f(acc[r][t][2] + b0v), silu_f(acc[r][t][3] + b1v), h, l);
                shh[row1 * NHP + kpo] = h;
                shl[row1 * NHP + kpo] = l;
            }
        }
    }
    __syncthreads();

    {
        float acc[2][6][4];
        #pragma unroll
        for (int r = 0; r < 2; ++r)
            #pragma unroll
            for (int t = 0; t < 6; ++t)
                #pragma unroll
                for (int c = 0; c < 4; ++c) acc[r][t][c] = 0.f;

        #pragma unroll 1
        for (int k0 = 0; k0 < H3; k0 += 16) {
            int kp = k0 >> 1;
            u32 bh[6][2];
            #pragma unroll
            for (int t = 0; t < 6; ++t) {
                int col = nbase + t * 8 + gid;
                bh[t][0] = __ldg(&g_i2h[(kp + tig) * H3 + col]);
                bh[t][1] = __ldg(&g_i2h[(kp + 4 + tig) * H3 + col]);
            }
            #pragma unroll
            for (int r = 0; r < 2; ++r) {
                int loff = (r * 16 + (lane & 15)) * NHP + kp + ((lane >> 4) << 2);
                u32 ah0, ah1, ah2, ah3, al0, al1, al2, al3;
                ldsm_x4(ah0, ah1, ah2, ah3, &shh[loff]);
                ldsm_x4(al0, al1, al2, al3, &shl[loff]);
                #pragma unroll
                for (int t = 0; t < 6; ++t) {
                    mma_f16(acc[r][t][0], acc[r][t][1], acc[r][t][2], acc[r][t][3],
                            ah0, ah1, ah2, ah3, bh[t][0], bh[t][1]);
                    mma_f16(acc[r][t][0], acc[r][t][1], acc[r][t][2], acc[r][t][3],
                            al0, al1, al2, al3, bh[t][0], bh[t][1]);
                }
            }
        }
        #pragma unroll
        for (int r = 0; r < 2; ++r) {
            int row0 = r * 16 + gid;
            int row1 = row0 + 8;
            #pragma unroll
            for (int t = 0; t < 6; ++t) {
                int col = nbase + t * 8 + 2 * tig;
                float b0v = __ldg(&b2[col]);
                float b1v = __ldg(&b2[col + 1]);
                if (n0 + row0 < NN)
                    *(__half2*)&g_x16[(size_t)(n0 + row0) * H3 + col] =
                        __floats2half2_rn(acc[r][t][0] + b0v, acc[r][t][1] + b1v);
                if (n0 + row1 < NN)
                    *(__half2*)&g_x16[(size_t)(n0 + row1) * H3 + col] =
                        __floats2half2_rn(acc[r][t][2] + b0v, acc[r][t][3] + b1v);
            }
        }
    }
}

// ---------------- edge filter MLP (R15 proven) ----------------
#define KPS 68
#define RKP 20
__global__ __launch_bounds__(256) void k_edge_filter(
    const float* __restrict__ rbf, const float* __restrict__ cut,
    const float* __restrict__ bf1, const float* __restrict__ bf2)
{
    __shared__ float scut[64];
    __shared__ int   spos[64];
    __shared__ u32 srbh[64 * RKP];
    __shared__ u32 srbl[64 * RKP];
    __shared__ u32 shiT[64 * KPS];
    __shared__ u32 sloT[64 * KPS];
    int tid = threadIdx.x;
    int e0 = blockIdx.x * 64;

    for (int i = tid; i < 64 * 16; i += 256) {
        int r = i >> 4, kp = i & 15;
        float v0 = 0.f, v1 = 0.f;
        if (kp < 10) {
            v0 = rbf[(e0 + r) * NR + 2 * kp];
            v1 = rbf[(e0 + r) * NR + 2 * kp + 1];
        }
        u32 h, l;
        split_pair_f16(v0, v1, h, l);
        srbh[r * RKP + kp] = h;
        srbl[r * RKP + kp] = l;
    }
    if (tid < 64) {
        scut[tid] = cut[e0 + tid];
        spos[tid] = g_epos[e0 + tid];
    }
    __syncthreads();

    int wid  = tid >> 5;
    int lane = tid & 31;
    int gid  = lane >> 2;
    int tig  = lane & 3;

    {
        int rb1 = (wid >> 1) * 16;
        int cb  = (wid & 1) * 64;
        float a1[8][4];
        #pragma unroll
        for (int t = 0; t < 8; ++t)
            #pragma unroll
            for (int c = 0; c < 4; ++c) a1[t][c] = 0.f;

        #pragma unroll
        for (int ks = 0; ks < 2; ++ks) {
            int kp = ks * 8;
            u32 bh1[8][2];
            #pragma unroll
            for (int t = 0; t < 8; ++t) {
                int col = cb + t * 8 + gid;
                bh1[t][0] = __ldg(&g_f1h[(kp + tig) * HH + col]);
                bh1[t][1] = __ldg(&g_f1h[(kp + 4 + tig) * HH + col]);
            }
            int loff = (rb1 + (lane & 15)) * RKP + kp + ((lane >> 4) << 2);
            u32 ah0, ah1, ah2, ah3, al0, al1, al2, al3;
            ldsm_x4(ah0, ah1, ah2, ah3, &srbh[loff]);
            ldsm_x4(al0, al1, al2, al3, &srbl[loff]);
            #pragma unroll
            for (int t = 0; t < 8; ++t) {
                mma_f16(a1[t][0], a1[t][1], a1[t][2], a1[t][3],
                        ah0, ah1, ah2, ah3, bh1[t][0], bh1[t][1]);
                mma_f16(a1[t][0], a1[t][1], a1[t][2], a1[t][3],
                        al0, al1, al2, al3, bh1[t][0], bh1[t][1]);
            }
        }
        #pragma unroll
        for (int t = 0; t < 8; ++t) {
            int col = cb + t * 8 + 2 * tig;
            int kpo = col >> 1;
            float b0v = __ldg(&bf1[col]);
            float b1v = __ldg(&bf1[col + 1]);
            int row0 = rb1 + gid;
            int row1 = row0 + 8;
            u32 h, l;
            split_pair_f16(silu_f(a1[t][0] + b0v), silu_f(a1[t][1] + b1v), h, l);
            shiT[row0 * KPS + kpo] = h;
            sloT[row0 * KPS + kpo] = l;
            split_pair_f16(silu_f(a1[t][2] + b0v), silu_f(a1[t][3] + b1v), h, l);
            shiT[row1 * KPS + kpo] = h;
            sloT[row1 * KPS + kpo] = l;
        }
    }
    __syncthreads();

    int nbase = wid * 48;

    float acc[4][6][4];
    #pragma unroll
    for (int r = 0; r < 4; ++r)
        #pragma unroll
        for (int t = 0; t < 6; ++t)
            #pragma unroll
            for (int c = 0; c < 4; ++c) acc[r][t][c] = 0.f;

    #pragma unroll 1
    for (int k0 = 0; k0 < HH; k0 += 16) {
        int kp = k0 >> 1;
        u32 bh[6][2];
        #pragma unroll
        for (int t = 0; t < 6; ++t) {
            int col = nbase + t * 8 + gid;
            bh[t][0] = __ldg(&g_bhp[(kp + tig) * H3 + col]);
            bh[t][1] = __ldg(&g_bhp[(kp + 4 + tig) * H3 + col]);
        }
        #pragma unroll
        for (int r = 0; r < 4; ++r) {
            int loff = (r * 16 + (lane & 15)) * KPS + kp + ((lane >> 4) << 2);
            u32 ah0, ah1, ah2, ah3, al0, al1, al2, al3;
            ldsm_x4(ah0, ah1, ah2, ah3, &shiT[loff]);
            ldsm_x4(al0, al1, al2, al3, &sloT[loff]);
            #pragma unroll
            for (int t = 0; t < 6; ++t) {
                mma_f16(acc[r][t][0], acc[r][t][1], acc[r][t][2], acc[r][t][3],
                        ah0, ah1, ah2, ah3, bh[t][0], bh[t][1]);
                mma_f16(acc[r][t][0], acc[r][t][1], acc[r][t][2], acc[r][t][3],
                        al0, al1, al2, al3, bh[t][0], bh[t][1]);
            }
        }
    }

    #pragma unroll
    for (int r = 0; r < 4; ++r) {
        int row0 = r * 16 + gid;
        int row1 = row0 + 8;
        float c0v = scut[row0];
        float c1v = scut[row1];
        size_t p0 = (size_t)spos[row0] * H3;
        size_t p1 = (size_t)spos[row1] * H3;
        #pragma unroll
        for (int t = 0; t < 6; ++t) {
            int col = nbase + t * 8 + 2 * tig;
            float b0v = bf2[col];
            float b1v = bf2[col + 1];
            __half2 v0 = __floats2half2_rn((acc[r][t][0] + b0v) * c0v,
                                           (acc[r][t][1] + b1v) * c0v);
            __half2 v1 = __floats2half2_rn((acc[r][t][2] + b0v) * c1v,
                                           (acc[r][t][3] + b1v) * c1v);
            *(__half2*)&g_filters[p0 + col] = v0;
            *(__half2*)&g_filters[p1 + col] = v1;
        }
    }
}

// ---------------- pull aggregation: vectorized, fp16 x/mu gathers ----------------
__global__ __launch_bounds__(128) void k_aggregate(
    const float* __restrict__ q, const float* __restrict__ mu)
{
    int node = blockIdx.x * 2 + (threadIdx.x >> 6);
    int hp = threadIdx.x & 63;
    if (node >= NN) return;
    int beg = g_off[node], end = g_off[node + 1];
    float2 qa = {0.f, 0.f};
    float2 m0 = {0.f, 0.f}, m1 = {0.f, 0.f}, m2 = {0.f, 0.f};
    for (int i = beg; i < end; ++i) {
        int s = g_src[i];
        const __half2* f = (const __half2*)&g_filters[(size_t)i * H3];
        float2 fq = __half22float2(f[hp]);
        float2 fr = __half22float2(f[64 + hp]);
        float2 fm = __half22float2(f[128 + hp]);
        const __half2* xs = (const __half2*)&g_x16[s * H3];
        float2 x0 = __half22float2(xs[hp]);
        float2 x1 = __half22float2(xs[64 + hp]);
        float2 x2 = __half22float2(xs[128 + hp]);
        float4 u = g_uv4[i];
        const __half2* ms = (const __half2*)&g_mu16[s * 3 * HH];
        float2 u0  = __half22float2(ms[hp]);
        float2 u1v = __half22float2(ms[64 + hp]);
        float2 u2v = __half22float2(ms[128 + hp]);
        float xrx = x1.x * fr.x, xry = x1.y * fr.y;
        float xmx = x2.x * fm.x, xmy = x2.y * fm.y;
        qa.x += x0.x * fq.x;
        qa.y += x0.y * fq.y;
        m0.x = fmaf(u.x, xrx, fmaf(u0.x,  xmx, m0.x));
        m0.y = fmaf(u.x, xry, fmaf(u0.y,  xmy, m0.y));
        m1.x = fmaf(u.y, xrx, fmaf(u1v.x, xmx, m1.x));
        m1.y = fmaf(u.y, xry, fmaf(u1v.y, xmy, m1.y));
        m2.x = fmaf(u.z, xrx, fmaf(u2v.x, xmx, m2.x));
        m2.y = fmaf(u.z, xry, fmaf(u2v.y, xmy, m2.y));
    }
    {
        float2 qv = *(const float2*)&q[node * HH + 2 * hp];
        *(float2*)&g_qmid[node * HH + 2 * hp] = make_float2(qv.x + qa.x, qv.y + qa.y);
        const float2* mb = (const float2*)&mu[node * 3 * HH];
        float2 b0 = mb[hp], b1 = mb[64 + hp], b2 = mb[128 + hp];
        float2* out = (float2*)&g_mumid[node * 3 * HH];
        out[hp]       = make_float2(b0.x + m0.x, b0.y + m0.y);
        out[64 + hp]  = make_float2(b1.x + m1.x, b1.y + m1.y);
        out[128 + hp] = make_float2(b2.x + m2.x, b2.y + m2.y);
    }
}

// ---------------- equivariant linear: pre-split A + ldmatrix (R16 proven) ----------------
#define EKP 68
#define EOP 260
#define EQ_SMEM ((2 * 48 * EKP) * 4 + 48 * EOP * 4)
__global__ __launch_bounds__(256) void k_equiv()
{
    extern __shared__ u32 sme[];
    u32* smh = sme;
    u32* sml = smh + 48 * EKP;
    float* sout = (float*)(sml + 48 * EKP);
    int tid = threadIdx.x;
    int n0 = blockIdx.x * 16;
    int row_base = n0 * 3;

    for (int i = tid; i < 48 * 64; i += 256) {
        int r = i >> 6, kp = i & 63;
        int grow = row_base + r;
        float2 v = (grow < NN * 3) ? *(const float2*)&g_mumid[grow * HH + 2 * kp]
                                   : make_float2(0.f, 0.f);
        u32 h, l;
        split_pair_f16(v.x, v.y, h, l);
        smh[r * EKP + kp] = h;
        sml[r * EKP + kp] = l;
    }
    __syncthreads();

    int wid  = tid >> 5;
    int lane = tid & 31;
    int gid  = lane >> 2;
    int tig  = lane & 3;
    int nbase = wid * 32;

    float acc[3][4][4];
    #pragma unroll
    for (int r = 0; r < 3; ++r)
        #pragma unroll
        for (int t = 0; t < 4; ++t)
            #pragma unroll
            for (int c = 0; c < 4; ++c) acc[r][t][c] = 0.f;

    #pragma unroll 1
    for (int k0 = 0; k0 < HH; k0 += 16) {
        int kp = k0 >> 1;
        u32 bh[4][2];
        #pragma unroll
        for (int t = 0; t < 4; ++t) {
            int col = nbase + t * 8 + gid;
            bh[t][0] = __ldg(&g_vch[(kp + tig) * H2 + col]);
            bh[t][1] = __ldg(&g_vch[(kp + 4 + tig) * H2 + col]);
        }
        #pragma unroll
        for (int r = 0; r < 3; ++r) {
            int loff = (r * 16 + (lane & 15)) * EKP + kp + ((lane >> 4) << 2);
            u32 ah0, ah1, ah2, ah3, al0, al1, al2, al3;
            ldsm_x4(ah0, ah1, ah2, ah3, &smh[loff]);
            ldsm_x4(al0, al1, al2, al3, &sml[loff]);
            #pragma unroll
            for (int t = 0; t < 4; ++t) {
                mma_f16(acc[r][t][0], acc[r][t][1], acc[r][t][2], acc[r][t][3],
                        ah0, ah1, ah2, ah3, bh[t][0], bh[t][1]);
                mma_f16(acc[r][t][0], acc[r][t][1], acc[r][t][2], acc[r][t][3],
                        al0, al1, al2, al3, bh[t][0], bh[t][1]);
            }
        }
    }

    #pragma unroll
    for (int r = 0; r < 3; ++r) {
        int row0 = r * 16 + gid;
        int row1 = row0 + 8;
        #pragma unroll
        for (int t = 0; t < 4; ++t) {
            int col = nbase + t * 8 + 2 * tig;
            sout[row0 * EOP + col]     = acc[r][t][0];
            sout[row0 * EOP + col + 1] = acc[r][t][1];
            sout[row1 * EOP + col]     = acc[r][t][2];
            sout[row1 * EOP + col + 1] = acc[r][t][3];
        }
    }
    __syncthreads();

    for (int slot = tid; slot < 16 * HH; slot += 256) {
        int r = slot >> 7;
        int o = slot & 127;
        int n = n0 + r;
        if (n >= NN) break;
        float v0 = sout[(r * 3 + 0) * EOP + o];
        float v1 = sout[(r * 3 + 1) * EOP + o];
        float v2 = sout[(r * 3 + 2) * EOP + o];
        float w0 = sout[(r * 3 + 0) * EOP + HH + o];
        float w1 = sout[(r * 3 + 1) * EOP + HH + o];
        float w2 = sout[(r * 3 + 2) * EOP + HH + o];
        g_vnorm[n * HH + o] = sqrtf(v0 * v0 + v1 * v1 + v2 * v2 + 1e-8f);
        g_inner[n * HH + o] = v0 * w0 + v1 * w1 + v2 * w2;
        g_muw[n * 3 * HH + o]          = w0;
        g_muw[n * 3 * HH + HH + o]     = w1;
        g_muw[n * 3 * HH + 2 * HH + o] = w2;
    }
}

// ---------------- scalar mix MLP: pre-split A + ldmatrix (R16 proven) ----------------
#define MAP 132
#define MHP 196
#define MDP 388
#define MIX_SMEM ((2 * 32 * MAP + 2 * 32 * MHP) * 4)
__global__ __launch_bounds__(256) void k_mix(
    const float* __restrict__ bm1, const float* __restrict__ bm2,
    float* __restrict__ qout, float* __restrict__ muout)
{
    extern __shared__ u32 smx[];
    u32* sAh = smx;
    u32* sAl = sAh + 32 * MAP;
    u32* sBh = sAl + 32 * MAP;
    u32* sBl = sBh + 32 * MHP;
    float* sD = (float*)sBh;
    int tid = threadIdx.x;
    int n0 = blockIdx.x * 32;

    for (int i = tid; i < 32 * 128; i += 256) {
        int r = i >> 7, kp = i & 127;
        int n = n0 + r;
        float2 v = make_float2(0.f, 0.f);
        if (n < NN)
            v = (kp < 64) ? *(const float2*)&g_qmid[n * HH + 2 * kp]
                          : *(const float2*)&g_vnorm[n * HH + 2 * (kp - 64)];
        u32 h, l;
        split_pair_f16(v.x, v.y, h, l);
        sAh[r * MAP + kp] = h;
        sAl[r * MAP + kp] = l;
    }
    __syncthreads();

    int wid  = tid >> 5;
    int lane = tid & 31;
    int gid  = lane >> 2;
    int tig  = lane & 3;
    int nbase = wid * 48;

    {
        float acc[2][6][4];
        #pragma unroll
        for (int r = 0; r < 2; ++r)
            #pragma unroll
            for (int t = 0; t < 6; ++t)
                #pragma unroll
                for (int c = 0; c < 4; ++c) acc[r][t][c] = 0.f;

        #pragma unroll 1
        for (int k0 = 0; k0 < H2; k0 += 16) {
            int kp = k0 >> 1;
            u32 bh[6][2];
            #pragma unroll
            for (int t = 0; t < 6; ++t) {
                int col = nbase + t * 8 + gid;
                bh[t][0] = __ldg(&g_m1h[(kp + tig) * H3 + col]);
                bh[t][1] = __ldg(&g_m1h[(kp + 4 + tig) * H3 + col]);
            }
            #pragma unroll
            for (int r = 0; r < 2; ++r) {
                int loff = (r * 16 + (lane & 15)) * MAP + kp + ((lane >> 4) << 2);
                u32 ah0, ah1, ah2, ah3, al0, al1, al2, al3;
                ldsm_x4(ah0, ah1, ah2, ah3, &sAh[loff]);
                ldsm_x4(al0, al1, al2, al3, &sAl[loff]);
                #pragma unroll
                for (int t = 0; t < 6; ++t) {
                    mma_f16(acc[r][t][0], acc[r][t][1], acc[r][t][2], acc[r][t][3],
                            ah0, ah1, ah2, ah3, bh[t][0], bh[t][1]);
                    mma_f16(acc[r][t][0], acc[r][t][1], acc[r][t][2], acc[r][t][3],
                            al0, al1, al2, al3, bh[t][0], bh[t][1]);
                }
            }
        }
        #pragma unroll
        for (int r = 0; r < 2; ++r) {
            int row0 = r * 16 + gid;
            int row1 = row0 + 8;
            #pragma unroll
            for (int t = 0; t < 6; ++t) {
                int col = nbase + t * 8 + 2 * tig;
                int kpo = col >> 1;
                float b0v = __ldg(&bm1[col]);
                float b1v = __ldg(&bm1[col + 1]);
                u32 h, l;
                split_pair_f16(silu_f(acc[r][t][0] + b0v), silu_f(acc[r][t][1] + b1v), h, l);
                sBh[row0 * MHP + kpo] = h;
                sBl[row0 * MHP + kpo] = l;
                split_pair_f16(silu_f(acc[r][t][2] + b0v), silu_f(acc[r][t][3] + b1v), h, l);
                sBh[row1 * MHP + kpo] = h;
                sBl[row1 * MHP + kpo] = l;
            }
        }
    }
    __syncthreads();

    {
        float acc[2][6][4];
        #pragma unroll
        for (int r = 0; r < 2; ++r)
            #pragma unroll
            for (int t = 0; t < 6; ++t)
                #pragma unroll
                for (int c = 0; c < 4; ++c) acc[r][t][c] = 0.f;

        #pragma unroll 1
        for (int k0 = 0; k0 < H3; k0 += 16) {
            int kp = k0 >> 1;
            u32 bh[6][2];
            #pragma unroll
            for (int t = 0; t < 6; ++t) {
                int col = nbase + t * 8 + gid;
                bh[t][0] = __ldg(&g_m2h[(kp + tig) * H3 + col]);
                bh[t][1] = __ldg(&g_m2h[(kp + 4 + tig) * H3 + col]);
            }
            #pragma unroll
            for (int r = 0; r < 2; ++r) {
                int loff = (r * 16 + (lane & 15)) * MHP + kp + ((lane >> 4) << 2);
                u32 ah0, ah1, ah2, ah3, al0, al1, al2, al3;
                ldsm_x4(ah0, ah1, ah2, ah3, &sBh[loff]);
                ldsm_x4(al0, al1, al2, al3, &sBl[loff]);
                #pragma unroll
                for (int t = 0; t < 6; ++t) {
                    mma_f16(acc[r][t][0], acc[r][t][1], acc[r][t][2], acc[r][t][3],
                            ah0, ah1, ah2, ah3, bh[t][0], bh[t][1]);
                    mma_f16(acc[r][t][0], acc[r][t][1], acc[r][t][2], acc[r][t][3],
                            al0, al1, al2, al3, bh[t][0], bh[t][1]);
                }
            }
        }
        __syncthreads();
        #pragma unroll
        for (int r = 0; r < 2; ++r) {
            int row0 = r * 16 + gid;
            int row1 = row0 + 8;
            #pragma unroll
            for (int t = 0; t < 6; ++t) {
                int col = nbase + t * 8 + 2 * tig;
                float b0v = __ldg(&bm2[col]);
                float b1v = __ldg(&bm2[col + 1]);
                sD[row0 * MDP + col]     = acc[r][t][0] + b0v;
                sD[row0 * MDP + col + 1] = acc[r][t][1] + b1v;
                sD[row1 * MDP + col]     = acc[r][t][2] + b0v;
                sD[row1 * MDP + col + 1] = acc[r][t][3] + b1v;
            }
        }
    }
    __syncthreads();

    for (int slot = tid; slot < 32 * HH; slot += 256) {
        int r = slot >> 7;
        int o = slot & 127;
        int n = n0 + r;
        if (n >= NN) break;
        float dq  = sD[r * MDP + o];
        float dms = sD[r * MDP + HH + o];
        float dqm = sD[r * MDP + 2 * HH + o];
        qout[n * HH + o] = g_qmid[n * HH + o] + dq + dqm * g_inner[n * HH + o];
        #pragma unroll
        for (int d = 0; d < 3; ++d) {
            int idx = n * 3 * HH + d * HH + o;
            muout[idx] = g_mumid[idx] + g_muw[idx] * dms;
        }
    }
}

// ---------------- launch ----------------
extern "C" void kernel_launch(void* const* d_in, const int* in_sizes, int n_in,
                              void* d_out, int out_size)
{
    const float* q   = (const float*)d_in[0];
    const float* mu  = (const float*)d_in[1];
    const int*   ei  = (const int*)d_in[2];
    const float* rbf = (const float*)d_in[3];
    const float* uv  = (const float*)d_in[4];
    const float* cut = (const float*)d_in[5];
    const float* Wi1 = (const float*)d_in[6];
    const float* bi1 = (const float*)d_in[7];
    const float* Wi2 = (const float*)d_in[8];
    const float* bi2 = (const float*)d_in[9];
    const float* Wf1 = (const float*)d_in[10];
    const float* bf1 = (const float*)d_in[11];
    const float* Wf2 = (const float*)d_in[12];
    const float* bf2 = (const float*)d_in[13];
    const float* Wv  = (const float*)d_in[14];
    const float* Wm1 = (const float*)d_in[15];
    const float* bm1 = (const float*)d_in[16];
    const float* Wm2 = (const float*)d_in[17];
    const float* bm2 = (const float*)d_in[18];

    float* qout  = (float*)d_out;
    float* muout = qout + (size_t)NN * HH;

    cudaFuncSetAttribute(k_node_mlp, cudaFuncAttributeMaxDynamicSharedMemorySize, NODE_SMEM);
    cudaFuncSetAttribute(k_equiv,    cudaFuncAttributeMaxDynamicSharedMemorySize, EQ_SMEM);
    cudaFuncSetAttribute(k_mix,      cudaFuncAttributeMaxDynamicSharedMemorySize, MIX_SMEM);

    k_prep<<<(SEG8 + 255) / 256, 256>>>(Wf2, Wi1, Wi2, Wv, Wm1, Wm2, Wf1, mu);
    k_count<<<512, 256>>>(ei);
    k_scan<<<1, 1024>>>();
    k_fill<<<512, 256>>>(ei, uv);

    k_node_mlp<<<(NN + 31) / 32, 256, NODE_SMEM>>>(q, bi1, bi2);
    k_edge_filter<<<NE / 64, 256>>>(rbf, cut, bf1, bf2);

    k_aggregate<<<(NN + 1) / 2, 128>>>(q, mu);

    k_equiv<<<(NN + 15) / 16, 256, EQ_SMEM>>>();
    k_mix<<<(NN + 31) / 32, 256, MIX_SMEM>>>(bm1, bm2, qout, muout);
}